// round 16
// baseline (speedup 1.0000x reference)
#include <cuda_runtime.h>
#include <cstddef>
#include <cstdint>

#define Bc 16
#define Fc 4
#define Kc 16
#define KH 8          // k's per block (k-half)
#define Yc 16
#define Xc 16
#define Pc 16
#define Tc 8
#define NT 1024
#define SLAB_FLOATS (Yc * Xc * Pc * Tc)      // 32768
#define SLAB_BYTES  (SLAB_FLOATS * 4)        // 131072

typedef unsigned long long u64;

// sm_103a packed f32x2 ops (PTX-only; ptxas never auto-fuses these)
__device__ __forceinline__ u64 pk2(float lo, float hi) {
    u64 r; asm("mov.b64 %0, {%1,%2};" : "=l"(r) : "f"(lo), "f"(hi)); return r;
}
__device__ __forceinline__ void unpk2(u64 v, float& lo, float& hi) {
    asm("mov.b64 {%0,%1}, %2;" : "=f"(lo), "=f"(hi) : "l"(v));
}
__device__ __forceinline__ u64 fma2_(u64 a, u64 b, u64 c) {
    u64 d; asm("fma.rn.f32x2 %0, %1, %2, %3;" : "=l"(d) : "l"(a), "l"(b), "l"(c)); return d;
}
__device__ __forceinline__ u64 mul2_(u64 a, u64 b) {
    u64 d; asm("mul.rn.f32x2 %0, %1, %2;" : "=l"(d) : "l"(a), "l"(b)); return d;
}
__device__ __forceinline__ uint32_t smem_u32(const void* p) {
    uint32_t a;
    asm("{ .reg .u64 t; cvta.to.shared.u64 t, %1; cvt.u32.u64 %0, t; }"
        : "=r"(a) : "l"(p));
    return a;
}

// One block = (b, f, k-half), 1024 threads = (yh:2b, x:4b, p:4b).
// The block's full 128KB (b,f) field slab is pulled into dynamic smem by a
// bulk-async copy (4 x 32KB cp.async.bulk, issued by tid 0 at kernel entry,
// completing on an mbarrier). The expf/means/integral setup runs UNDER the
// copy; the main loop (R13 body verbatim) then reads conflict-free LDS.128
// instead of stalling on DRAM. Epilogue: R14 deferred-winv finalization.
__global__ void __launch_bounds__(NT, 1) pkl_fused(
    const float* __restrict__ field, const float* __restrict__ darea,
    const float* __restrict__ dlev,  const float* __restrict__ dtime,
    const float* __restrict__ lat_mean, const float* __restrict__ lat_logstd,
    const float* __restrict__ lon_mean, const float* __restrict__ lon_logstd,
    const float* __restrict__ lev_mean, const float* __restrict__ lev_logstd,
    const float* __restrict__ time_logtau, float* __restrict__ out)
{
    extern __shared__ __align__(16) float sfield[];   // SLAB_BYTES

    int blk = blockIdx.x;
    int kh = blk & 1;
    int f  = (blk >> 1) & 3;
    int b  = blk >> 3;
    int tid  = threadIdx.x;
    int lane = tid & 31;
    int warp = tid >> 5;

    __shared__ __align__(16) float sklat[Yc][KH];
    __shared__ __align__(16) float sklon[Xc][KH];
    __shared__ __align__(16) float sklev[Pc][KH];
    __shared__ float srate[KH];
    __shared__ float sdamean[Yc * Xc], sda[Yc * Xc];
    __shared__ float sdlmean[Pc], sdl[Pc], sdtm[Tc], sdt[Tc];
    __shared__ float sred[32][KH];
    __shared__ float sint[8][KH];          // per-warp partial Syx
    __shared__ __align__(8) unsigned long long smbar;

    // ---- issue the bulk-async slab copy immediately (tid 0) ----
    if (tid == 0) {
        uint32_t bar = smem_u32(&smbar);
        asm volatile("mbarrier.init.shared.b64 [%0], 1;" :: "r"(bar) : "memory");
        asm volatile("fence.proxy.async.shared::cta;" ::: "memory");
        asm volatile("mbarrier.arrive.expect_tx.shared.b64 _, [%0], %1;"
                     :: "r"(bar), "r"((uint32_t)SLAB_BYTES) : "memory");
        const char* gsrc = (const char*)(field + (size_t)(b * Fc + f) * SLAB_FLOATS);
        uint32_t dst = smem_u32(sfield);
        #pragma unroll
        for (int c = 0; c < 4; c++) {
            asm volatile(
                "cp.async.bulk.shared::cluster.global.mbarrier::complete_tx::bytes "
                "[%0], [%1], %2, [%3];"
                :: "r"(dst + c * 32768), "l"(gsrc + (size_t)c * 32768),
                   "r"(32768u), "r"(bar)
                : "memory");
        }
    }

    // ================= setup phase (runs under the bulk copy) ==============
    if (tid < 3 * 16 * KH) {
        int j   = tid & 7;
        int d   = (tid >> 3) & 15;
        int dim = tid >> 7;
        int fk  = f * Kc + kh * KH + j;
        float coord = -1.0f + 2.0f * (float)d / 15.0f;
        float m, ls;
        if (dim == 0)      { m = lat_mean[fk]; ls = lat_logstd[fk]; }
        else if (dim == 1) { m = lon_mean[fk]; ls = lon_logstd[fk]; }
        else               { m = lev_mean[fk]; ls = lev_logstd[fk]; }
        float z = (coord - m) * expf(-ls);
        float g = expf(-0.5f * z * z);
        if (dim == 0)      sklat[d][j] = g;
        else if (dim == 1) sklon[d][j] = g;
        else               sklev[d][j] = g;
    }
    if (tid >= 512 && tid < 512 + KH) {
        int j = tid - 512;
        int fk = f * Kc + kh * KH + j;
        float tau = expf(time_logtau[fk]) + 1e-4f;
        srate[j] = expf(-1.0f / tau);       // ktime[t] = rate^t
    }
    if (tid >= 768) {
        int i = tid - 768;
        float s = 0.f;
        #pragma unroll
        for (int bb = 0; bb < Bc; bb++) s += darea[bb * 256 + i];
        sdamean[i] = s * (1.f / 16.f);
        sda[i] = darea[b * 256 + i];
    }
    if (tid >= 704 && tid < 704 + Pc) {
        int i = tid - 704;
        float s = 0.f;
        #pragma unroll
        for (int bb = 0; bb < Bc; bb++) s += dlev[bb * Pc + i];
        sdlmean[i] = s * (1.f / 16.f);
        sdl[i] = dlev[b * Pc + i];
    }
    if (tid >= 736 && tid < 736 + Tc) {
        int i = tid - 736;
        float s = 0.f;
        #pragma unroll
        for (int bb = 0; bb < Bc; bb++) s += dtime[bb * Tc + i];
        sdtm[i] = s * (1.f / 16.f);
        sdt[i] = dtime[b * Tc + i];
    }
    __syncthreads();   // tables + mbarrier-init visible to all

    // ---- integral partials (warps 0-7; consumed in the finalizer) ----
    if (warp < 8) {
        int yi = tid >> 4, xi = tid & 15;  // tid < 256 here
        float dm = sdamean[tid];
        #pragma unroll
        for (int j = 0; j < KH; j++) {
            float v = dm * sklat[yi][j] * sklon[xi][j];
            #pragma unroll
            for (int o = 16; o > 0; o >>= 1) v += __shfl_xor_sync(0xFFFFFFFFu, v, o);
            if (lane == 0) sint[warp][j] = v;
        }
    }

    // ---- wait for the slab copy ----
    {
        uint32_t bar = smem_u32(&smbar);
        for (;;) {
            uint32_t done;
            asm volatile(
                "{\n\t.reg .pred P;\n\t"
                "mbarrier.try_wait.parity.acquire.cta.shared::cta.b64 P, [%1], %2, 0x989680;\n\t"
                "selp.b32 %0, 1, 0, P;\n\t}"
                : "=r"(done) : "r"(bar), "r"(0u) : "memory");
            if (done) break;
        }
    }

    // ================= main contraction (R13 body, smem-sourced) ===========
    int p  = tid & 15;
    int x  = (tid >> 4) & 15;
    int yh = tid >> 8;                     // 0..3
    u64 rate2[4];
    #pragma unroll
    for (int jj = 0; jj < 4; jj++)
        rate2[jj] = pk2(srate[2 * jj], srate[2 * jj + 1]);
    float dtr[Tc];
    #pragma unroll
    for (int t = 0; t < Tc; t++) dtr[t] = sdt[t];
    u64 acc[4];
    #pragma unroll
    for (int jj = 0; jj < 4; jj++) acc[jj] = pk2(0.f, 0.f);

    const float4* srow = (const float4*)(sfield
        + (size_t)((yh * 4) * Xc * Pc + x * Pc + p) * Tc);
    // y-stride = 2048 floats = 512 float4

    #pragma unroll
    for (int yy = 0; yy < 4; yy++) {
        float4 a0 = srow[yy * 512];
        float4 a1 = srow[yy * 512 + 1];
        int y = yh * 4 + yy;
        float ft0 = a0.x * dtr[0], ft1 = a0.y * dtr[1];
        float ft2 = a0.z * dtr[2], ft3 = a0.w * dtr[3];
        float ft4 = a1.x * dtr[4], ft5 = a1.y * dtr[5];
        float ft6 = a1.z * dtr[6], ft7 = a1.w * dtr[7];
        u64 fb[8];
        fb[0] = pk2(ft0, ft0); fb[1] = pk2(ft1, ft1);
        fb[2] = pk2(ft2, ft2); fb[3] = pk2(ft3, ft3);
        fb[4] = pk2(ft4, ft4); fb[5] = pk2(ft5, ft5);
        fb[6] = pk2(ft6, ft6); fb[7] = pk2(ft7, ft7);
        float dav = sda[y * 16 + x];
        u64 da2 = pk2(dav, dav);
        const u64* klrow = (const u64*)&sklat[y][0];   // 8B-aligned LDS.64
        #pragma unroll
        for (int jj = 0; jj < 4; jj++) {
            u64 wy = mul2_(klrow[jj], da2);            // klat[y]*darea, k-pair
            u64 dd = fb[7];
            #pragma unroll
            for (int t = 6; t >= 0; t--) dd = fma2_(dd, rate2[jj], fb[t]);
            acc[jj] = fma2_(wy, dd, acc[jj]);
        }
    }

    // (x,p)-dependent factor applied once, after the y/t loop
    float dlp = sdl[p];
    float av[KH];
    #pragma unroll
    for (int jj = 0; jj < 4; jj++) {
        u64 pre = pk2(sklon[x][2 * jj]     * sklev[p][2 * jj]     * dlp,
                      sklon[x][2 * jj + 1] * sklev[p][2 * jj + 1] * dlp);
        u64 r = mul2_(pre, acc[jj]);
        unpk2(r, av[2 * jj], av[2 * jj + 1]);
    }

    // ---- deterministic block reduction: shfl + fixed-order shared sum ----
    #pragma unroll
    for (int j = 0; j < KH; j++) {
        float v = av[j];
        #pragma unroll
        for (int o = 16; o > 0; o >>= 1) v += __shfl_xor_sync(0xFFFFFFFFu, v, o);
        if (lane == 0) sred[warp][j] = v;
    }
    __syncthreads();

    // ---- finalize: Syx/Sp/St -> winv, scale, store (8 threads) ----
    if (tid < KH) {
        float s = 0.f;
        #pragma unroll
        for (int w = 0; w < 32; w++) s += sred[w][tid];
        float Syx = 0.f;
        #pragma unroll
        for (int w = 0; w < 8; w++) Syx += sint[w][tid];
        float Sp = 0.f;
        #pragma unroll
        for (int pp = 0; pp < Pc; pp++) Sp = fmaf(sklev[pp][tid], sdlmean[pp], Sp);
        float r = srate[tid];
        float St = sdtm[Tc - 1];
        #pragma unroll
        for (int t = Tc - 2; t >= 0; t--) St = fmaf(St, r, sdtm[t]);
        float winv = 1.0f / (Syx * Sp * St + 1e-4f);
        out[b * (Fc * Kc) + f * Kc + kh * KH + tid] = s * winv;
    }
}

extern "C" void kernel_launch(void* const* d_in, const int* in_sizes, int n_in,
                              void* d_out, int out_size)
{
    cudaFuncSetAttribute(pkl_fused,
                         cudaFuncAttributeMaxDynamicSharedMemorySize, SLAB_BYTES);
    pkl_fused<<<Bc * Fc * 2, NT, SLAB_BYTES>>>(
        (const float*)d_in[0], (const float*)d_in[1],
        (const float*)d_in[2], (const float*)d_in[3],
        (const float*)d_in[4], (const float*)d_in[5],
        (const float*)d_in[6], (const float*)d_in[7],
        (const float*)d_in[8], (const float*)d_in[9],
        (const float*)d_in[10], (float*)d_out);
}